// round 7
// baseline (speedup 1.0000x reference)
#include <cuda_runtime.h>
#include <cstdint>

// ---------------------------------------------------------------------------
// Shapes (fixed): B=4, N=M=P=2048, NS=1024
//   d_in[0] pc1_0 [4,2048,3]  d_in[1] pc1_1 [4,1024,3]  d_in[2] pc1_3 [4,2048,1]
//   d_in[3] pc2   [4,2048,3]  d_in[4] pc3   [4,2048,3]  out [4,2048,2048] f32
//
// out[b,n,m] = S + 0.5*dist(pc1_0[b,n], pc2[b,m])
// S = conf + 0.5*cd(flat pc1_0||pc2) + seed_cd(flat pc1_1||pc2)
// ---------------------------------------------------------------------------

typedef unsigned long long u64;

// partial min-d2 scratch (chunk-major), no atomics:
//  slot0: 16*8192  @0       cd dir1 (q=pc2,  R=pc1_0)
//  slot1: 16*8192  @131072  cd dir2 (q=pc1_0,R=pc2)
//  slot2:  8*8192  @262144  seed d1 (q=pc2,  R=pc1_1)
//  slot3: 16*4096  @327680  seed d2 (q=pc1_1,R=pc2)
//  slot4: 16*2048  @393216  conf    (per-b:  q=pc3,  R=pc2)
__device__ float g_part[425984];
__device__ float g_scal[3];    // [0]=cd [1]=seed [2]=conf

// ------------------- f32x2 helpers: u64-resident, zero-mov -------------------
__device__ __forceinline__ u64 pk2(float lo, float hi) {
    u64 r; asm("mov.b64 %0,{%1,%2};" : "=l"(r) : "f"(lo), "f"(hi)); return r;
}
__device__ __forceinline__ u64 f2fma(u64 a, u64 b, u64 c) {
    u64 d; asm("fma.rn.f32x2 %0,%1,%2,%3;" : "=l"(d) : "l"(a), "l"(b), "l"(c));
    return d;
}
__device__ __forceinline__ u64 f2add(u64 a, u64 b) {
    u64 d; asm("add.rn.f32x2 %0,%1,%2;" : "=l"(d) : "l"(a), "l"(b));
    return d;
}
// final fma of a chain: returns unpacked halves
__device__ __forceinline__ float2 f2fma_out(u64 a, u64 b, u64 c) {
    float2 r;
    asm("{.reg .b64 D;\n\t"
        "fma.rn.f32x2 D,%2,%3,%4;\n\t"
        "mov.b64 {%0,%1},D;}"
        : "=f"(r.x), "=f"(r.y) : "l"(a), "l"(b), "l"(c));
    return r;
}
__device__ __forceinline__ float fsqrt_ap(float x) {
    float r; asm("sqrt.approx.f32 %0,%1;" : "=f"(r) : "f"(x)); return r;
}

// -------------------------------- init --------------------------------------
__global__ void init_kernel() {
    if (threadIdx.x < 3) g_scal[threadIdx.x] = 0.0f;
}

// --------------------------- fused NN min pass -------------------------------
// 832 blocks x 256 threads. Block = (task, 512-query block, 512-R chunk).
// 2 queries/thread. R chunk in smem packed per 2 points as 4 u64:
//   {x0x1}{y0y1} | {z0z1}{r2_0 r2_1}
// Accumulate min(r^2 - 2 a.r); epilogue adds a^2, clamps, writes partial.
__global__ void __launch_bounds__(256) nn_fused(const float* __restrict__ pc10,
                                                const float* __restrict__ pc11,
                                                const float* __restrict__ pc2,
                                                const float* __restrict__ pc3)
{
    __shared__ u64 tile[1024];
    const int t = threadIdx.x;
    int l = blockIdx.x;

    const float* Q; const float* R; float* part; int qb, rc;
    if (l < 256)      { Q = pc2;  R = pc10; qb = l >> 4; rc = l & 15;
                        part = g_part +          rc * 8192 + qb * 512; }
    else if (l < 512) { l -= 256; Q = pc10; R = pc2;  qb = l >> 4; rc = l & 15;
                        part = g_part + 131072 + rc * 8192 + qb * 512; }
    else if (l < 640) { l -= 512; Q = pc2;  R = pc11; qb = l >> 3; rc = l & 7;
                        part = g_part + 262144 + rc * 8192 + qb * 512; }
    else if (l < 768) { l -= 640; Q = pc11; R = pc2;  qb = l >> 4; rc = l & 15;
                        part = g_part + 327680 + rc * 4096 + qb * 512; }
    else              { l -= 768; const int b = l >> 4; const int r = l & 15;
                        qb = r >> 2; rc = r & 3;
                        Q = pc3 + b * 6144; R = pc2 + b * 6144;
                        part = g_part + 393216 + (b * 4 + rc) * 2048 + qb * 512; }

    // ---- stage chunk: thread t packs R points (2t, 2t+1) of this chunk ----
    {
        const float* rp = R + (size_t)rc * 1536 + t * 6;   // 512 pts * 3
        const float2 p0 = *(const float2*)(rp + 0);   // x0 y0
        const float2 p1 = *(const float2*)(rp + 2);   // z0 x1
        const float2 p2 = *(const float2*)(rp + 4);   // y1 z1
        const float r20 = p0.x * p0.x + p0.y * p0.y + p1.x * p1.x;
        const float r21 = p1.y * p1.y + p2.x * p2.x + p2.y * p2.y;
        ulonglong2* T2 = (ulonglong2*)tile;
        T2[2 * t]     = make_ulonglong2(pk2(p0.x, p1.y), pk2(p0.y, p2.x));
        T2[2 * t + 1] = make_ulonglong2(pk2(p1.x, p2.y), pk2(r20, r21));
    }

    // ---- two queries per thread ----
    const int q0 = qb * 512 + t;
    const int q1 = q0 + 256;
    const float ax0 = Q[3 * q0], ay0 = Q[3 * q0 + 1], az0 = Q[3 * q0 + 2];
    const float ax1 = Q[3 * q1], ay1 = Q[3 * q1 + 1], az1 = Q[3 * q1 + 2];
    const float a20 = ax0 * ax0 + ay0 * ay0 + az0 * az0;
    const float a21 = ax1 * ax1 + ay1 * ay1 + az1 * az1;
    const u64 nax0 = pk2(-2.f * ax0, -2.f * ax0);
    const u64 nay0 = pk2(-2.f * ay0, -2.f * ay0);
    const u64 naz0 = pk2(-2.f * az0, -2.f * az0);
    const u64 nax1 = pk2(-2.f * ax1, -2.f * ax1);
    const u64 nay1 = pk2(-2.f * ay1, -2.f * ay1);
    const u64 naz1 = pk2(-2.f * az1, -2.f * az1);

    float m0a = 3.0e38f, m0b = 3.0e38f, m1a = 3.0e38f, m1b = 3.0e38f;

    __syncthreads();

    const ulonglong2* T2 = (const ulonglong2*)tile;
    #pragma unroll 8
    for (int g = 0; g < 256; g++) {
        const ulonglong2 A = T2[2 * g];       // {xx, yy}
        const ulonglong2 B = T2[2 * g + 1];   // {zz, ww}
        const float2 t0 = f2fma_out(nax0, A.x,
                          f2fma(nay0, A.y, f2fma(naz0, B.x, B.y)));
        const float2 t1 = f2fma_out(nax1, A.x,
                          f2fma(nay1, A.y, f2fma(naz1, B.x, B.y)));
        m0a = fminf(m0a, t0.x);  m0b = fminf(m0b, t0.y);
        m1a = fminf(m1a, t1.x);  m1b = fminf(m1b, t1.y);
    }

    part[t]       = fmaxf(fminf(m0a, m0b) + a20, 0.0f);
    part[t + 256] = fmaxf(fminf(m1a, m1b) + a21, 0.0f);
}

// ------------------------------ finalize ------------------------------------
// 36864 threads: reduce partial mins over chunks -> sqrt -> weighted sums.
__global__ void __launch_bounds__(256) finalize_kernel(const float* __restrict__ pc13)
{
    __shared__ float s[3];
    if (threadIdx.x < 3) s[threadIdx.x] = 0.0f;
    __syncthreads();

    const int i = blockIdx.x * 256 + threadIdx.x;
    float val; int cat;
    if (i < 8192) {                     // cd dir1
        float m = 3.0e38f;
        #pragma unroll
        for (int c = 0; c < 16; c++) m = fminf(m, g_part[c * 8192 + i]);
        val = sqrtf(m) * (1.0f / 8192.0f); cat = 0;
    } else if (i < 16384) {             // cd dir2
        const int q = i - 8192; float m = 3.0e38f;
        #pragma unroll
        for (int c = 0; c < 16; c++) m = fminf(m, g_part[131072 + c * 8192 + q]);
        val = sqrtf(m) * (1.0f / 8192.0f); cat = 0;
    } else if (i < 24576) {             // seed dir1
        const int q = i - 16384; float m = 3.0e38f;
        #pragma unroll
        for (int c = 0; c < 8; c++) m = fminf(m, g_part[262144 + c * 8192 + q]);
        val = sqrtf(m) * (1.0f / 8192.0f); cat = 1;
    } else if (i < 28672) {             // seed dir2
        const int q = i - 24576; float m = 3.0e38f;
        #pragma unroll
        for (int c = 0; c < 16; c++) m = fminf(m, g_part[327680 + c * 4096 + q]);
        val = sqrtf(m) * (1.0f / 4096.0f); cat = 1;
    } else {                            // confidence
        const int q = i - 28672;        // b*2048 + p
        const int b = q >> 11, p = q & 2047;
        float m = 3.0e38f;
        #pragma unroll
        for (int c = 0; c < 4; c++) m = fminf(m, g_part[393216 + (b * 4 + c) * 2048 + p]);
        const float gt = expf(-sqrtf(m));
        const float df = pc13[q] - gt;
        val = df * df * (1.0f / 8192.0f); cat = 2;
    }
    atomicAdd(&s[cat], val);
    __syncthreads();
    if (threadIdx.x < 3) atomicAdd(&g_scal[threadIdx.x], s[threadIdx.x]);
}

// ------------------------------ out kernel ----------------------------------
// 1024 blocks x 256 threads. Block = (b, 8-row n chunk). Thread register-caches
// 8 pc2 points (4 packed u64 groups), loops 8 n rows; distance f32x2-packed,
// sqrt via MUFU sqrt.approx (525k warp-ops total -> ~3.5us chip, overlapped).
__global__ void __launch_bounds__(256) out_kernel(const float* __restrict__ pc10,
                                                  const float* __restrict__ pc2,
                                                  float* __restrict__ out)
{
    __shared__ float4 qs[8];             // per n: {nax, nay, naz, a2}
    const int t = threadIdx.x;
    const int b  = blockIdx.x >> 8;
    const int nc = blockIdx.x & 255;
    const int nbase = b * 2048 + nc * 8;

    // ---- register cache: 8 pc2 points (m = 8t .. 8t+7), packed per 2 pts ----
    float F[24];
    {
        const float4* rp = (const float4*)(pc2 + (size_t)b * 6144 + t * 24);
        #pragma unroll
        for (int j = 0; j < 6; j++) {
            const float4 f = rp[j];
            F[4 * j] = f.x; F[4 * j + 1] = f.y; F[4 * j + 2] = f.z; F[4 * j + 3] = f.w;
        }
    }
    u64 Gx[4], Gy[4], Gz[4], Gw[4];
    #pragma unroll
    for (int g = 0; g < 4; g++) {
        const float x0 = F[6 * g], y0 = F[6 * g + 1], z0 = F[6 * g + 2];
        const float x1 = F[6 * g + 3], y1 = F[6 * g + 4], z1 = F[6 * g + 5];
        Gx[g] = pk2(x0, x1);
        Gy[g] = pk2(y0, y1);
        Gz[g] = pk2(z0, z1);
        Gw[g] = pk2(x0 * x0 + y0 * y0 + z0 * z0,
                    x1 * x1 + y1 * y1 + z1 * z1);
    }

    // ---- stage 8 queries ----
    if (t < 8) {
        const int n = nbase + t;
        const float x = pc10[3 * n], y = pc10[3 * n + 1], z = pc10[3 * n + 2];
        qs[t] = make_float4(-2.f * x, -2.f * y, -2.f * z, x * x + y * y + z * z);
    }
    const float S = g_scal[2] + 0.5f * g_scal[0] + g_scal[1];
    __syncthreads();

    float* orow = out + (size_t)nbase * 2048 + 8 * t;
    #pragma unroll
    for (int n = 0; n < 8; n++) {
        const float4 q = qs[n];
        const u64 nx = pk2(q.x, q.x);
        const u64 ny = pk2(q.y, q.y);
        const u64 nz = pk2(q.z, q.z);
        const u64 a2 = pk2(q.w, q.w);
        float res[8];
        #pragma unroll
        for (int g = 0; g < 4; g++) {
            const float2 d2 = f2fma_out(nx, Gx[g],
                              f2fma(ny, Gy[g],
                              f2fma(nz, Gz[g], f2add(a2, Gw[g]))));
            const float s0 = fsqrt_ap(fmaxf(d2.x, 0.0f));
            const float s1 = fsqrt_ap(fmaxf(d2.y, 0.0f));
            res[2 * g]     = fmaf(0.5f, s0, S);
            res[2 * g + 1] = fmaf(0.5f, s1, S);
        }
        ((float4*)orow)[0] = make_float4(res[0], res[1], res[2], res[3]);
        ((float4*)orow)[1] = make_float4(res[4], res[5], res[6], res[7]);
        orow += 2048;
    }
}

// ------------------------------ launcher ------------------------------------
extern "C" void kernel_launch(void* const* d_in, const int* in_sizes, int n_in,
                              void* d_out, int out_size)
{
    const float* pc10 = (const float*)d_in[0];
    const float* pc11 = (const float*)d_in[1];
    const float* pc13 = (const float*)d_in[2];
    const float* pc2  = (const float*)d_in[3];
    const float* pc3  = (const float*)d_in[4];
    float* out = (float*)d_out;

    init_kernel<<<1, 32>>>();
    nn_fused<<<832, 256>>>(pc10, pc11, pc2, pc3);
    finalize_kernel<<<144, 256>>>(pc13);
    out_kernel<<<1024, 256>>>(pc10, pc2, out);
}

// round 9
// speedup vs baseline: 1.5193x; 1.5193x over previous
#include <cuda_runtime.h>
#include <cstdint>

// ---------------------------------------------------------------------------
// Shapes (fixed): B=4, N=M=P=2048, NS=1024
//   d_in[0] pc1_0 [4,2048,3]  d_in[1] pc1_1 [4,1024,3]  d_in[2] pc1_3 [4,2048,1]
//   d_in[3] pc2   [4,2048,3]  d_in[4] pc3   [4,2048,3]  out [4,2048,2048] f32
//
// out[b,n,m] = S + 0.5*dist(pc1_0[b,n], pc2[b,m])
// S = conf + 0.5*cd(flat pc1_0||pc2) + seed_cd(flat pc1_1||pc2)
// All math scalar FFMA (f32x2 regressed twice: R6 ~neutral, R7 1.6x worse).
// ---------------------------------------------------------------------------

// partial min-d2 scratch (chunk-major), no atomics:
//  slot0: 16*8192  @0       cd dir1 (q=pc2,  R=pc1_0)
//  slot1: 16*8192  @131072  cd dir2 (q=pc1_0,R=pc2)
//  slot2:  8*8192  @262144  seed d1 (q=pc2,  R=pc1_1)
//  slot3: 16*4096  @327680  seed d2 (q=pc1_1,R=pc2)
//  slot4: 16*2048  @393216  conf    (per-b:  q=pc3,  R=pc2)
__device__ float g_part[425984];
__device__ float g_scal[3];    // [0]=cd [1]=seed [2]=conf

__device__ __forceinline__ float fsqrt_ap(float x) {
    float r; asm("sqrt.approx.f32 %0,%1;" : "=f"(r) : "f"(x)); return r;
}

// -------------------------------- init --------------------------------------
__global__ void init_kernel() {
    if (threadIdx.x < 3) g_scal[threadIdx.x] = 0.0f;
}

// --------------------------- fused NN min pass -------------------------------
// 832 blocks x 256 threads. Block = (task, 512-query block, 512-R chunk).
// 2 queries/thread, 2 min accumulators each (even/odd R) for ILP.
// tile[j] = {x, y, z, |r|^2}; accumulate min(r^2 - 2 a.r); add a^2 at end.
__global__ void __launch_bounds__(256) nn_fused(const float* __restrict__ pc10,
                                                const float* __restrict__ pc11,
                                                const float* __restrict__ pc2,
                                                const float* __restrict__ pc3)
{
    __shared__ float4 tile[512];
    const int t = threadIdx.x;
    int l = blockIdx.x;

    const float* Q; const float* R; float* part; int qb, rc;
    if (l < 256)      { Q = pc2;  R = pc10; qb = l >> 4; rc = l & 15;
                        part = g_part +          rc * 8192 + qb * 512; }
    else if (l < 512) { l -= 256; Q = pc10; R = pc2;  qb = l >> 4; rc = l & 15;
                        part = g_part + 131072 + rc * 8192 + qb * 512; }
    else if (l < 640) { l -= 512; Q = pc2;  R = pc11; qb = l >> 3; rc = l & 7;
                        part = g_part + 262144 + rc * 8192 + qb * 512; }
    else if (l < 768) { l -= 640; Q = pc11; R = pc2;  qb = l >> 4; rc = l & 15;
                        part = g_part + 327680 + rc * 4096 + qb * 512; }
    else              { l -= 768; const int b = l >> 4; const int r = l & 15;
                        qb = r >> 2; rc = r & 3;
                        Q = pc3 + b * 6144; R = pc2 + b * 6144;
                        part = g_part + 393216 + (b * 4 + rc) * 2048 + qb * 512; }

    // ---- stage chunk: 2 points per thread ----
    {
        const float* rp = R + (size_t)rc * 1536;   // 512 pts * 3 floats
        #pragma unroll
        for (int j = 0; j < 2; j++) {
            const int idx = t + j * 256;
            const float x = rp[3 * idx], y = rp[3 * idx + 1], z = rp[3 * idx + 2];
            tile[idx] = make_float4(x, y, z, x * x + y * y + z * z);
        }
    }

    // ---- two queries per thread ----
    const int q0 = qb * 512 + t;
    const int q1 = q0 + 256;
    const float ax0 = Q[3 * q0], ay0 = Q[3 * q0 + 1], az0 = Q[3 * q0 + 2];
    const float ax1 = Q[3 * q1], ay1 = Q[3 * q1 + 1], az1 = Q[3 * q1 + 2];
    const float a20 = ax0 * ax0 + ay0 * ay0 + az0 * az0;
    const float a21 = ax1 * ax1 + ay1 * ay1 + az1 * az1;
    const float nax0 = -2.f * ax0, nay0 = -2.f * ay0, naz0 = -2.f * az0;
    const float nax1 = -2.f * ax1, nay1 = -2.f * ay1, naz1 = -2.f * az1;

    float m0a = 3.0e38f, m0b = 3.0e38f, m1a = 3.0e38f, m1b = 3.0e38f;

    __syncthreads();

    #pragma unroll 4
    for (int g = 0; g < 512; g += 2) {
        const float4 r0 = tile[g];
        const float4 r1 = tile[g + 1];
        m0a = fminf(m0a, fmaf(nax0, r0.x, fmaf(nay0, r0.y, fmaf(naz0, r0.z, r0.w))));
        m1a = fminf(m1a, fmaf(nax1, r0.x, fmaf(nay1, r0.y, fmaf(naz1, r0.z, r0.w))));
        m0b = fminf(m0b, fmaf(nax0, r1.x, fmaf(nay0, r1.y, fmaf(naz0, r1.z, r1.w))));
        m1b = fminf(m1b, fmaf(nax1, r1.x, fmaf(nay1, r1.y, fmaf(naz1, r1.z, r1.w))));
    }

    part[t]       = fmaxf(fminf(m0a, m0b) + a20, 0.0f);
    part[t + 256] = fmaxf(fminf(m1a, m1b) + a21, 0.0f);
}

// ------------------------------ finalize ------------------------------------
// 36864 threads: reduce partial mins over chunks -> sqrt -> weighted sums.
__global__ void __launch_bounds__(256) finalize_kernel(const float* __restrict__ pc13)
{
    __shared__ float s[3];
    if (threadIdx.x < 3) s[threadIdx.x] = 0.0f;
    __syncthreads();

    const int i = blockIdx.x * 256 + threadIdx.x;
    float val; int cat;
    if (i < 8192) {                     // cd dir1
        float m = 3.0e38f;
        #pragma unroll
        for (int c = 0; c < 16; c++) m = fminf(m, g_part[c * 8192 + i]);
        val = sqrtf(m) * (1.0f / 8192.0f); cat = 0;
    } else if (i < 16384) {             // cd dir2
        const int q = i - 8192; float m = 3.0e38f;
        #pragma unroll
        for (int c = 0; c < 16; c++) m = fminf(m, g_part[131072 + c * 8192 + q]);
        val = sqrtf(m) * (1.0f / 8192.0f); cat = 0;
    } else if (i < 24576) {             // seed dir1
        const int q = i - 16384; float m = 3.0e38f;
        #pragma unroll
        for (int c = 0; c < 8; c++) m = fminf(m, g_part[262144 + c * 8192 + q]);
        val = sqrtf(m) * (1.0f / 8192.0f); cat = 1;
    } else if (i < 28672) {             // seed dir2
        const int q = i - 24576; float m = 3.0e38f;
        #pragma unroll
        for (int c = 0; c < 16; c++) m = fminf(m, g_part[327680 + c * 4096 + q]);
        val = sqrtf(m) * (1.0f / 4096.0f); cat = 1;
    } else {                            // confidence
        const int q = i - 28672;        // b*2048 + p
        const int b = q >> 11, p = q & 2047;
        float m = 3.0e38f;
        #pragma unroll
        for (int c = 0; c < 4; c++) m = fminf(m, g_part[393216 + (b * 4 + c) * 2048 + p]);
        const float gt = expf(-sqrtf(m));
        const float df = pc13[q] - gt;
        val = df * df * (1.0f / 8192.0f); cat = 2;
    }
    atomicAdd(&s[cat], val);
    __syncthreads();
    if (threadIdx.x < 3) atomicAdd(&g_scal[threadIdx.x], s[threadIdx.x]);
}

// ------------------------------ out kernel ----------------------------------
// Grid 740 = 148*5 (one balanced wave @5 blocks/SM), 256 threads.
// Row grid-stride: block handles rows {bid, bid+740, ...} (~11 rows).
// Thread register-caches 8 pc2 points of the row's batch (reloaded on b
// change, <=3 times per block); per row: 8 elems, scalar FFMA + MUFU sqrt,
// two coalesced STG.128.
#define OUT_GRID 740
__global__ void __launch_bounds__(256, 5) out_kernel(const float* __restrict__ pc10,
                                                     const float* __restrict__ pc2,
                                                     float* __restrict__ out)
{
    const int t = threadIdx.x;
    const float S = g_scal[2] + 0.5f * g_scal[0] + g_scal[1];

    float Gx[8], Gy[8], Gz[8], Gr[8];
    int cb = -1;

    for (int row = blockIdx.x; row < 8192; row += OUT_GRID) {
        const int b = row >> 11;
        if (b != cb) {
            cb = b;
            // 8 points: m = 8t .. 8t+7 -> 24 floats = 6 float4
            const float4* rp = (const float4*)(pc2 + (size_t)b * 6144 + t * 24);
            float F[24];
            #pragma unroll
            for (int j = 0; j < 6; j++) {
                const float4 f = rp[j];
                F[4 * j] = f.x; F[4 * j + 1] = f.y;
                F[4 * j + 2] = f.z; F[4 * j + 3] = f.w;
            }
            #pragma unroll
            for (int g = 0; g < 8; g++) {
                Gx[g] = F[3 * g]; Gy[g] = F[3 * g + 1]; Gz[g] = F[3 * g + 2];
                Gr[g] = Gx[g] * Gx[g] + Gy[g] * Gy[g] + Gz[g] * Gz[g];
            }
        }

        const float ax = pc10[3 * row], ay = pc10[3 * row + 1], az = pc10[3 * row + 2];
        const float a2 = ax * ax + ay * ay + az * az;
        const float nax = -2.f * ax, nay = -2.f * ay, naz = -2.f * az;

        float res[8];
        #pragma unroll
        for (int g = 0; g < 8; g++) {
            const float d2 = fmaf(nax, Gx[g], fmaf(nay, Gy[g],
                             fmaf(naz, Gz[g], Gr[g] + a2)));
            res[g] = fmaf(0.5f, fsqrt_ap(fmaxf(d2, 0.0f)), S);
        }
        float* o = out + (size_t)row * 2048 + 8 * t;
        ((float4*)o)[0] = make_float4(res[0], res[1], res[2], res[3]);
        ((float4*)o)[1] = make_float4(res[4], res[5], res[6], res[7]);
    }
}

// ------------------------------ launcher ------------------------------------
extern "C" void kernel_launch(void* const* d_in, const int* in_sizes, int n_in,
                              void* d_out, int out_size)
{
    const float* pc10 = (const float*)d_in[0];
    const float* pc11 = (const float*)d_in[1];
    const float* pc13 = (const float*)d_in[2];
    const float* pc2  = (const float*)d_in[3];
    const float* pc3  = (const float*)d_in[4];
    float* out = (float*)d_out;

    init_kernel<<<1, 32>>>();
    nn_fused<<<832, 256>>>(pc10, pc11, pc2, pc3);
    finalize_kernel<<<144, 256>>>(pc13);
    out_kernel<<<OUT_GRID, 256>>>(pc10, pc2, out);
}

// round 11
// speedup vs baseline: 1.5285x; 1.0061x over previous
#include <cuda_runtime.h>
#include <cstdint>

// ---------------------------------------------------------------------------
// Shapes (fixed): B=4, N=M=P=2048, NS=1024
//   d_in[0] pc1_0 [4,2048,3]  d_in[1] pc1_1 [4,1024,3]  d_in[2] pc1_3 [4,2048,1]
//   d_in[3] pc2   [4,2048,3]  d_in[4] pc3   [4,2048,3]  out [4,2048,2048] f32
//
// out[b,n,m] = S + 0.5*dist(pc1_0[b,n], pc2[b,m])
// S = conf + 0.5*cd(flat pc1_0||pc2) + seed_cd(flat pc1_1||pc2)
// All math scalar FFMA; sqrt via MUFU sqrt.approx (rel_err 5.7e-8 verified).
// ---------------------------------------------------------------------------

// partial min-d2 scratch (chunk-major), no atomics:
//  slot0: 16*8192  @0       cd dir1 (q=pc2,  R=pc1_0)
//  slot1: 16*8192  @131072  cd dir2 (q=pc1_0,R=pc2)
//  slot2:  8*8192  @262144  seed d1 (q=pc2,  R=pc1_1)
//  slot3: 16*4096  @327680  seed d2 (q=pc1_1,R=pc2)
//  slot4: 16*2048  @393216  conf    (per-b:  q=pc3,  R=pc2)
__device__ float g_part[425984];
__device__ float g_scal[3];    // [0]=cd [1]=seed [2]=conf

__device__ __forceinline__ float fsqrt_ap(float x) {
    float r; asm("sqrt.approx.f32 %0,%1;" : "=f"(r) : "f"(x)); return r;
}

// -------------------------------- init --------------------------------------
__global__ void init_kernel() {
    if (threadIdx.x < 3) g_scal[threadIdx.x] = 0.0f;
}

// --------------------------- fused NN min pass -------------------------------
// 832 blocks x 256 threads. Block = (task, 512-query block, 512-R chunk).
// 2 queries/thread, 2 min accumulators each (even/odd R) for ILP.
// tile[j] = {x, y, z, |r|^2}; accumulate min(r^2 - 2 a.r); add a^2 at end.
__global__ void __launch_bounds__(256) nn_fused(const float* __restrict__ pc10,
                                                const float* __restrict__ pc11,
                                                const float* __restrict__ pc2,
                                                const float* __restrict__ pc3)
{
    __shared__ float4 tile[512];
    const int t = threadIdx.x;
    int l = blockIdx.x;

    const float* Q; const float* R; float* part; int qb, rc;
    if (l < 256)      { Q = pc2;  R = pc10; qb = l >> 4; rc = l & 15;
                        part = g_part +          rc * 8192 + qb * 512; }
    else if (l < 512) { l -= 256; Q = pc10; R = pc2;  qb = l >> 4; rc = l & 15;
                        part = g_part + 131072 + rc * 8192 + qb * 512; }
    else if (l < 640) { l -= 512; Q = pc2;  R = pc11; qb = l >> 3; rc = l & 7;
                        part = g_part + 262144 + rc * 8192 + qb * 512; }
    else if (l < 768) { l -= 640; Q = pc11; R = pc2;  qb = l >> 4; rc = l & 15;
                        part = g_part + 327680 + rc * 4096 + qb * 512; }
    else              { l -= 768; const int b = l >> 4; const int r = l & 15;
                        qb = r >> 2; rc = r & 3;
                        Q = pc3 + b * 6144; R = pc2 + b * 6144;
                        part = g_part + 393216 + (b * 4 + rc) * 2048 + qb * 512; }

    // ---- stage chunk: 2 points per thread ----
    {
        const float* rp = R + (size_t)rc * 1536;   // 512 pts * 3 floats
        #pragma unroll
        for (int j = 0; j < 2; j++) {
            const int idx = t + j * 256;
            const float x = rp[3 * idx], y = rp[3 * idx + 1], z = rp[3 * idx + 2];
            tile[idx] = make_float4(x, y, z, x * x + y * y + z * z);
        }
    }

    // ---- two queries per thread ----
    const int q0 = qb * 512 + t;
    const int q1 = q0 + 256;
    const float ax0 = Q[3 * q0], ay0 = Q[3 * q0 + 1], az0 = Q[3 * q0 + 2];
    const float ax1 = Q[3 * q1], ay1 = Q[3 * q1 + 1], az1 = Q[3 * q1 + 2];
    const float a20 = ax0 * ax0 + ay0 * ay0 + az0 * az0;
    const float a21 = ax1 * ax1 + ay1 * ay1 + az1 * az1;
    const float nax0 = -2.f * ax0, nay0 = -2.f * ay0, naz0 = -2.f * az0;
    const float nax1 = -2.f * ax1, nay1 = -2.f * ay1, naz1 = -2.f * az1;

    float m0a = 3.0e38f, m0b = 3.0e38f, m1a = 3.0e38f, m1b = 3.0e38f;

    __syncthreads();

    #pragma unroll 4
    for (int g = 0; g < 512; g += 2) {
        const float4 r0 = tile[g];
        const float4 r1 = tile[g + 1];
        m0a = fminf(m0a, fmaf(nax0, r0.x, fmaf(nay0, r0.y, fmaf(naz0, r0.z, r0.w))));
        m1a = fminf(m1a, fmaf(nax1, r0.x, fmaf(nay1, r0.y, fmaf(naz1, r0.z, r0.w))));
        m0b = fminf(m0b, fmaf(nax0, r1.x, fmaf(nay0, r1.y, fmaf(naz0, r1.z, r1.w))));
        m1b = fminf(m1b, fmaf(nax1, r1.x, fmaf(nay1, r1.y, fmaf(naz1, r1.z, r1.w))));
    }

    part[t]       = fmaxf(fminf(m0a, m0b) + a20, 0.0f);
    part[t + 256] = fmaxf(fminf(m1a, m1b) + a21, 0.0f);
}

// ------------------------------ finalize ------------------------------------
// 36864 threads: reduce partial mins over chunks -> sqrt -> weighted sums.
__global__ void __launch_bounds__(256) finalize_kernel(const float* __restrict__ pc13)
{
    __shared__ float s[3];
    if (threadIdx.x < 3) s[threadIdx.x] = 0.0f;
    __syncthreads();

    const int i = blockIdx.x * 256 + threadIdx.x;
    float val; int cat;
    if (i < 8192) {                     // cd dir1
        float m = 3.0e38f;
        #pragma unroll
        for (int c = 0; c < 16; c++) m = fminf(m, g_part[c * 8192 + i]);
        val = sqrtf(m) * (1.0f / 8192.0f); cat = 0;
    } else if (i < 16384) {             // cd dir2
        const int q = i - 8192; float m = 3.0e38f;
        #pragma unroll
        for (int c = 0; c < 16; c++) m = fminf(m, g_part[131072 + c * 8192 + q]);
        val = sqrtf(m) * (1.0f / 8192.0f); cat = 0;
    } else if (i < 24576) {             // seed dir1
        const int q = i - 16384; float m = 3.0e38f;
        #pragma unroll
        for (int c = 0; c < 8; c++) m = fminf(m, g_part[262144 + c * 8192 + q]);
        val = sqrtf(m) * (1.0f / 8192.0f); cat = 1;
    } else if (i < 28672) {             // seed dir2
        const int q = i - 24576; float m = 3.0e38f;
        #pragma unroll
        for (int c = 0; c < 16; c++) m = fminf(m, g_part[327680 + c * 4096 + q]);
        val = sqrtf(m) * (1.0f / 4096.0f); cat = 1;
    } else {                            // confidence
        const int q = i - 28672;        // b*2048 + p
        const int b = q >> 11, p = q & 2047;
        float m = 3.0e38f;
        #pragma unroll
        for (int c = 0; c < 4; c++) m = fminf(m, g_part[393216 + (b * 4 + c) * 2048 + p]);
        const float gt = expf(-sqrtf(m));
        const float df = pc13[q] - gt;
        val = df * df * (1.0f / 8192.0f); cat = 2;
    }
    atomicAdd(&s[cat], val);
    __syncthreads();
    if (threadIdx.x < 3) atomicAdd(&g_scal[threadIdx.x], s[threadIdx.x]);
}

// ------------------------------ out kernel ----------------------------------
// R6 structure (the best measured): 512 blocks x 256 threads, block = (b, 16-row
// n chunk). Queries pre-staged in smem IN PARALLEL by 16 threads (kills the
// per-row serial LDG chain that made R7/R9 slower). 8 pc2 points register-
// cached per thread. Scalar FFMA + MUFU sqrt (replaces R6's packed Newton).
__global__ void __launch_bounds__(256) out_kernel(const float* __restrict__ pc10,
                                                  const float* __restrict__ pc2,
                                                  float* __restrict__ out)
{
    __shared__ float4 qs[16];            // per n: {nax, nay, naz, a2}
    const int t = threadIdx.x;
    const int b  = blockIdx.x >> 7;
    const int nc = blockIdx.x & 127;
    const int nbase = b * 2048 + nc * 16;

    // ---- register cache: 8 pc2 points (m = 8t .. 8t+7) ----
    float Gx[8], Gy[8], Gz[8], Gr[8];
    {
        float F[24];
        const float4* rp = (const float4*)(pc2 + (size_t)b * 6144 + t * 24);
        #pragma unroll
        for (int j = 0; j < 6; j++) {
            const float4 f = rp[j];
            F[4 * j] = f.x; F[4 * j + 1] = f.y;
            F[4 * j + 2] = f.z; F[4 * j + 3] = f.w;
        }
        #pragma unroll
        for (int g = 0; g < 8; g++) {
            Gx[g] = F[3 * g]; Gy[g] = F[3 * g + 1]; Gz[g] = F[3 * g + 2];
            Gr[g] = Gx[g] * Gx[g] + Gy[g] * Gy[g] + Gz[g] * Gz[g];
        }
    }

    // ---- stage 16 query rows in parallel ----
    if (t < 16) {
        const int n = nbase + t;
        const float x = pc10[3 * n], y = pc10[3 * n + 1], z = pc10[3 * n + 2];
        qs[t] = make_float4(-2.f * x, -2.f * y, -2.f * z, x * x + y * y + z * z);
    }
    const float S = g_scal[2] + 0.5f * g_scal[0] + g_scal[1];
    __syncthreads();

    float* orow = out + (size_t)nbase * 2048 + 8 * t;
    #pragma unroll 4
    for (int n = 0; n < 16; n++) {
        const float4 q = qs[n];
        float res[8];
        #pragma unroll
        for (int g = 0; g < 8; g++) {
            const float d2 = fmaf(q.x, Gx[g], fmaf(q.y, Gy[g],
                             fmaf(q.z, Gz[g], Gr[g] + q.w)));
            res[g] = fmaf(0.5f, fsqrt_ap(fmaxf(d2, 0.0f)), S);
        }
        ((float4*)orow)[0] = make_float4(res[0], res[1], res[2], res[3]);
        ((float4*)orow)[1] = make_float4(res[4], res[5], res[6], res[7]);
        orow += 2048;
    }
}

// ------------------------------ launcher ------------------------------------
extern "C" void kernel_launch(void* const* d_in, const int* in_sizes, int n_in,
                              void* d_out, int out_size)
{
    const float* pc10 = (const float*)d_in[0];
    const float* pc11 = (const float*)d_in[1];
    const float* pc13 = (const float*)d_in[2];
    const float* pc2  = (const float*)d_in[3];
    const float* pc3  = (const float*)d_in[4];
    float* out = (float*)d_out;

    init_kernel<<<1, 32>>>();
    nn_fused<<<832, 256>>>(pc10, pc11, pc2, pc3);
    finalize_kernel<<<144, 256>>>(pc13);
    out_kernel<<<512, 256>>>(pc10, pc2, out);
}